// round 3
// baseline (speedup 1.0000x reference)
#include <cuda_runtime.h>
#include <cuda_bf16.h>
#include <math.h>

#define TT 1024
#define NENV 8192
#define CHUNKS 32
#define STEPS 32            // TT / CHUNKS
#define ENVB 128            // envs (threads) per block
#define NEB (NENV / ENVB)   // 64 env-block columns
#define MTOT (TT * NENV)    // 8388608

#define GAMMA_F 0.99f
#define GL_F (0.99f * 0.95f)

// ---------------- scratch (device globals) -----------------------------------
__device__ float g_adv[MTOT];            // raw (unnormalized) advantages
__device__ float g_Aagg[CHUNKS * NENV];  // chunk affine aggregate A
__device__ float g_Bagg[CHUNKS * NENV];  // chunk affine aggregate B
__device__ float g_Pref[CHUNKS * NENV];  // inclusive prefix (g at chunk exit)
__device__ int   g_stat[CHUNKS * NEB];   // 0=none 1=aggregate 2=prefix
__device__ double g_acc[5];              // 0:sum 1:sumsq 2:vloss 3:ent 4:action

// ---------------- acquire/release helpers ------------------------------------
__device__ __forceinline__ int ld_acq(const int* p) {
    int v;
    asm volatile("ld.acquire.gpu.b32 %0, [%1];" : "=r"(v) : "l"(p) : "memory");
    return v;
}
__device__ __forceinline__ void st_rel(int* p, int v) {
    asm volatile("st.release.gpu.b32 [%0], %1;" :: "l"(p), "r"(v) : "memory");
}

// ---------------- block reduce (flexible warps) ------------------------------
template <int NWARP>
__device__ __forceinline__ float block_reduce(float v, float* smem) {
    #pragma unroll
    for (int o = 16; o > 0; o >>= 1) v += __shfl_down_sync(0xffffffffu, v, o);
    int lane = threadIdx.x & 31, w = threadIdx.x >> 5;
    if (lane == 0) smem[w] = v;
    __syncthreads();
    if (w == 0) {
        v = (lane < NWARP) ? smem[lane] : 0.0f;
        #pragma unroll
        for (int o = NWARP / 2; o > 0; o >>= 1) v += __shfl_down_sync(0xffffffffu, v, o);
    }
    return v; // valid on thread 0
}

// ---------------- K0: reset flags + accumulators -----------------------------
__global__ void k_init() {
    int i = blockIdx.x * blockDim.x + threadIdx.x;
    if (i < CHUNKS * NEB) g_stat[i] = 0;
    if (i < 5) g_acc[i] = 0.0;
}

// ---------------- K1: fused single-pass GAE scan + value loss + entropy ------
__global__ void __launch_bounds__(ENVB) k_scan(
    const float* __restrict__ rew, const float* __restrict__ masks,
    const float* __restrict__ bad, const float* __restrict__ vp,
    const float* __restrict__ lastv, const float* __restrict__ nval,
    const float* __restrict__ ent)
{
    __shared__ float sh_a[STEPS * ENVB];
    __shared__ float sh_b[STEPS * ENVB];
    __shared__ float sm0[4], sm1[4], sm2[4], sm3[4];

    const int tid = threadIdx.x;
    const int n   = blockIdx.x * ENVB + tid;
    const int p   = blockIdx.y;              // processing order (reverse T)
    const int c   = (CHUNKS - 1) - p;        // actual chunk along T
    const int lo  = c * STEPS, hi = lo + STEPS;

    // ---- phase 1: build per-step affine coeffs, compose chunk aggregate ----
    float v_next = (hi == TT) ? lastv[n] : vp[hi * NENV + n];
    float A = 1.0f, B = 0.0f;
    #pragma unroll 8
    for (int t = hi - 1; t >= lo; --t) {
        int idx = t * NENV + n;
        float v  = vp[idx];
        float m  = masks[idx + NENV];
        float bd = bad[idx + NENV];
        float r  = rew[idx];
        float delta = r + GAMMA_F * v_next * m - v;
        float a = GL_F * m * bd;
        float b = delta * bd;
        int ts = t - lo;
        sh_a[ts * ENVB + tid] = a;
        sh_b[ts * ENVB + tid] = b;
        B = a * B + b;      // (A,B) = f_t ∘ (A,B)
        A = a * A;
        v_next = v;
    }
    g_Aagg[p * NENV + n] = A;
    g_Bagg[p * NENV + n] = B;
    __syncthreads();
    __threadfence();
    if (tid == 0) st_rel(&g_stat[p * NEB + blockIdx.x], 1);

    // ---- decoupled look-back: resolve incoming gae -------------------------
    float g_in = 0.0f;
    if (p > 0) {
        float Ac = 1.0f, Bc = 0.0f;
        bool done = false;
        for (int q = p - 1; q >= 0 && !done; --q) {
            const int* sp = &g_stat[q * NEB + blockIdx.x];
            int s;
            do { s = ld_acq(sp); } while (s == 0);
            if (s == 2) {
                g_in = Ac * g_Pref[q * NENV + n] + Bc;
                done = true;
            } else {
                Bc += Ac * g_Bagg[q * NENV + n];
                Ac *= g_Aagg[q * NENV + n];
            }
        }
        if (!done) g_in = Bc;   // composed all the way to the start (g=0)
    }

    // publish inclusive prefix
    g_Pref[p * NENV + n] = A * g_in + B;
    __syncthreads();
    __threadfence();
    if (tid == 0) st_rel(&g_stat[p * NEB + blockIdx.x], 2);

    // ---- phase 2: replay from smem, write adv, fuse reductions -------------
    float g = g_in;
    float s = 0.f, s2 = 0.f, vl = 0.f, es = 0.f;
    #pragma unroll 8
    for (int t = hi - 1; t >= lo; --t) {
        int idx = t * NENV + n;
        int ts = t - lo;
        float a = sh_a[ts * ENVB + tid];
        float b = sh_b[ts * ENVB + tid];
        g = a * g + b;
        g_adv[idx] = g;
        s  += g;
        s2 += g * g;

        float v  = vp[idx];        // L2 hit (touched in phase 1)
        float nv = nval[idx];
        float en = ent[idx];
        float ret = g + v;
        float dc  = fminf(fmaxf(nv - v, -0.2f), 0.2f);
        float d1 = nv - ret, d2 = (v + dc) - ret;
        vl += fmaxf(d1 * d1, d2 * d2);
        es += en;
    }

    float rs  = block_reduce<4>(s,  sm0);
    float rs2 = block_reduce<4>(s2, sm1);
    float rvl = block_reduce<4>(vl, sm2);
    float res = block_reduce<4>(es, sm3);
    if (tid == 0) {
        atomicAdd(&g_acc[0], (double)rs);
        atomicAdd(&g_acc[1], (double)rs2);
        atomicAdd(&g_acc[2], (double)rvl);
        atomicAdd(&g_acc[3], (double)res);
    }
}

// ---------------- K2: action loss (stats folded in) --------------------------
__global__ void __launch_bounds__(256) k_action(
    const float* __restrict__ lp, const float* __restrict__ plp)
{
    __shared__ float sm[8];
    __shared__ float s_mean, s_istd;
    if (threadIdx.x == 0) {
        double S = g_acc[0], S2 = g_acc[1];
        double M = (double)MTOT;
        double mean = S / M;
        double var = (S2 - S * S / M) / (M - 1.0);
        s_mean = (float)mean;
        s_istd = (float)(1.0 / (sqrt(var) + 1e-5));
    }
    __syncthreads();
    float mean = s_mean, istd = s_istd;

    int i = blockIdx.x * blockDim.x + threadIdx.x; // float4 index
    const float4 gv = reinterpret_cast<const float4*>(g_adv)[i];
    const float4 lv = reinterpret_cast<const float4*>(lp)[i];
    const float4 pv = reinterpret_cast<const float4*>(plp)[i];

    float s = 0.0f;
    {
        float a = (gv.x - mean) * istd;
        float r = __expf(lv.x - pv.x);
        float rc = fminf(fmaxf(r, 0.8f), 1.2f);
        s += fminf(r * a, rc * a);
    }
    {
        float a = (gv.y - mean) * istd;
        float r = __expf(lv.y - pv.y);
        float rc = fminf(fmaxf(r, 0.8f), 1.2f);
        s += fminf(r * a, rc * a);
    }
    {
        float a = (gv.z - mean) * istd;
        float r = __expf(lv.z - pv.z);
        float rc = fminf(fmaxf(r, 0.8f), 1.2f);
        s += fminf(r * a, rc * a);
    }
    {
        float a = (gv.w - mean) * istd;
        float r = __expf(lv.w - pv.w);
        float rc = fminf(fmaxf(r, 0.8f), 1.2f);
        s += fminf(r * a, rc * a);
    }

    float rsum = block_reduce<8>(s, sm);
    if (threadIdx.x == 0) atomicAdd(&g_acc[4], (double)rsum);
}

// ---------------- K3: combine scalar loss ------------------------------------
__global__ void k_final(float* __restrict__ out) {
    double M = (double)MTOT;
    double value_loss = 0.5 * (g_acc[2] / M);
    double action_loss = -(g_acc[4] / M);
    double ent_mean = g_acc[3] / M;
    out[0] = (float)(value_loss * 0.5 + action_loss - 0.01 * ent_mean);
}

// ---------------- launch ------------------------------------------------------
extern "C" void kernel_launch(void* const* d_in, const int* in_sizes, int n_in,
                              void* d_out, int out_size)
{
    const float* rew   = (const float*)d_in[0];
    const float* masks = (const float*)d_in[1];
    const float* bad   = (const float*)d_in[2];
    const float* vp    = (const float*)d_in[3];
    const float* lastv = (const float*)d_in[4];
    const float* lp    = (const float*)d_in[5];
    const float* plp   = (const float*)d_in[6];
    const float* nval  = (const float*)d_in[7];
    const float* ent   = (const float*)d_in[8];
    float* out = (float*)d_out;

    k_init<<<(CHUNKS * NEB + 255) / 256, 256>>>();

    dim3 grid(NEB, CHUNKS);
    k_scan<<<grid, ENVB>>>(rew, masks, bad, vp, lastv, nval, ent);

    k_action<<<(MTOT / 4) / 256, 256>>>(lp, plp);
    k_final<<<1, 1>>>(out);
}

// round 4
// speedup vs baseline: 1.2370x; 1.2370x over previous
#include <cuda_runtime.h>
#include <cuda_bf16.h>
#include <math.h>

#define TT 1024
#define NENV 8192
#define CHUNKS 32
#define STEPS 32            // TT / CHUNKS
#define MTOT (TT * NENV)    // 8388608

#define GAMMA_F 0.99f
#define GLF (0.99f * 0.95f)

// ---------------- scratch (device globals) -----------------------------------
__device__ float    g_bv[MTOT];              // per-step b = delta * bad  (fp32)
__device__ unsigned g_abits[CHUNKS * NENV];  // per-step a!=0 bit, 32 steps/word
__device__ float    g_Ag[CHUNKS * NENV];     // chunk aggregate A
__device__ float    g_Bg[CHUNKS * NENV];     // chunk aggregate B
__device__ float    g_SA [CHUNKS * NENV];    // Σ A_t   (within chunk)
__device__ float    g_SB [CHUNKS * NENV];    // Σ B_t
__device__ float    g_SA2[CHUNKS * NENV];    // Σ A_t^2
__device__ float    g_SAB[CHUNKS * NENV];    // Σ A_t B_t
__device__ float    g_SB2[CHUNKS * NENV];    // Σ B_t^2
__device__ float    g_gin[CHUNKS * NENV];    // incoming gae per chunk
__device__ double   g_acc[5];                // 0:Σg 1:Σg² 2:vloss 3:ent 4:action
__device__ float    g_stats[2];              // mean, inv_std
__device__ unsigned g_tick1, g_tick2;        // last-block tickets

// ---------------- block reduce (256 threads = 8 warps) ------------------------
__device__ __forceinline__ float block_reduce(float v, float* smem) {
    #pragma unroll
    for (int o = 16; o > 0; o >>= 1) v += __shfl_down_sync(0xffffffffu, v, o);
    int lane = threadIdx.x & 31, w = threadIdx.x >> 5;
    if (lane == 0) smem[w] = v;
    __syncthreads();
    if (w == 0) {
        v = (lane < 8) ? smem[lane] : 0.0f;
        #pragma unroll
        for (int o = 4; o > 0; o >>= 1) v += __shfl_down_sync(0xffffffffu, v, o);
    }
    return v; // valid on thread 0
}

// ---------------- K0: reset accumulators + tickets ----------------------------
__global__ void k_init() {
    int i = threadIdx.x;
    if (i < 5) g_acc[i] = 0.0;
    if (i == 5) g_tick1 = 0u;
    if (i == 6) g_tick2 = 0u;
}

// ---------------- K1: coeff pass — b values, a-bits, aggregates, moments ------
__global__ void __launch_bounds__(256) k_coeff(
    const float* __restrict__ rew, const float* __restrict__ masks,
    const float* __restrict__ bad, const float* __restrict__ vp,
    const float* __restrict__ lastv)
{
    const int n  = blockIdx.x * 256 + threadIdx.x;
    const int c  = blockIdx.y;
    const int lo = c * STEPS, hi = lo + STEPS;

    float v_next = (hi == TT) ? lastv[n] : vp[hi * NENV + n];
    float A = 1.0f, B = 0.0f;
    float SA = 0.f, SB = 0.f, SA2 = 0.f, SAB = 0.f, SB2 = 0.f;
    unsigned bits = 0u;

    #pragma unroll 8
    for (int t = hi - 1; t >= lo; --t) {
        int idx = t * NENV + n;
        float v  = vp[idx];
        float m  = masks[idx + NENV];
        float bd = bad[idx + NENV];
        float r  = rew[idx];
        float delta = r + GAMMA_F * v_next * m - v;
        float a = GLF * m * bd;                 // exactly GLF or 0 (m,bd ∈ {0,1})
        float b = delta * bd;
        g_bv[idx] = b;
        bits |= (a != 0.0f ? 1u : 0u) << (t - lo);
        B = a * B + b;                          // (A,B) = f_t ∘ (A,B)
        A = a * A;
        SA += A;  SB += B;
        SA2 += A * A;  SAB += A * B;  SB2 += B * B;
        v_next = v;
    }
    int ci = c * NENV + n;
    g_abits[ci] = bits;
    g_Ag[ci] = A;   g_Bg[ci] = B;
    g_SA[ci] = SA;  g_SB[ci] = SB;
    g_SA2[ci] = SA2; g_SAB[ci] = SAB; g_SB2[ci] = SB2;
}

// ---------------- K2: chunk scan + exact Σg, Σg² + stats ----------------------
__global__ void __launch_bounds__(256) k_scan() {
    __shared__ float sm0[8], sm1[8];
    const int n = blockIdx.x * 256 + threadIdx.x;

    float g = 0.0f, sg = 0.0f, sg2 = 0.0f;
    #pragma unroll
    for (int c = CHUNKS - 1; c >= 0; --c) {
        int i = c * NENV + n;
        g_gin[i] = g;
        sg  += g_SA[i] * g + g_SB[i];
        sg2 += (g_SA2[i] * g + 2.0f * g_SAB[i]) * g + g_SB2[i];
        g = g_Ag[i] * g + g_Bg[i];
    }

    float rs  = block_reduce(sg,  sm0);
    float rs2 = block_reduce(sg2, sm1);
    if (threadIdx.x == 0) {
        atomicAdd(&g_acc[0], (double)rs);
        atomicAdd(&g_acc[1], (double)rs2);
        __threadfence();
        unsigned t = atomicAdd(&g_tick1, 1u);
        if (t == gridDim.x - 1) {
            volatile double* acc = g_acc;
            double S = acc[0], S2 = acc[1];
            double M = (double)MTOT;
            double mean = S / M;
            double var = (S2 - S * S / M) / (M - 1.0);
            g_stats[0] = (float)mean;
            g_stats[1] = (float)(1.0 / (sqrt(var) + 1e-5));
        }
    }
}

// ---------------- K3: fully fused main pass (no adv array!) -------------------
__global__ void __launch_bounds__(256) k_main(
    const float* __restrict__ vp,   const float* __restrict__ nval,
    const float* __restrict__ ent,  const float* __restrict__ lp,
    const float* __restrict__ plp,  float* __restrict__ out)
{
    __shared__ float sm0[8], sm1[8], sm2[8];
    const int n  = blockIdx.x * 256 + threadIdx.x;
    const int c  = blockIdx.y;
    const int lo = c * STEPS, hi = lo + STEPS;
    const int ci = c * NENV + n;

    const float mean = g_stats[0], istd = g_stats[1];
    float g = g_gin[ci];
    const unsigned bits = g_abits[ci];

    float vl = 0.f, es = 0.f, act = 0.f;
    #pragma unroll 8
    for (int t = hi - 1; t >= lo; --t) {
        int idx = t * NENV + n;
        float b = g_bv[idx];
        float am = ((bits >> (t - lo)) & 1u) ? GLF : 0.0f;
        g = fmaf(am, g, b);                      // gae recurrence

        // action loss
        float a = (g - mean) * istd;
        float r = __expf(lp[idx] - plp[idx]);
        float rc = fminf(fmaxf(r, 0.8f), 1.2f);
        act += fminf(r * a, rc * a);

        // value loss
        float v  = vp[idx];
        float nv = nval[idx];
        float ret = g + v;
        float dc  = fminf(fmaxf(nv - v, -0.2f), 0.2f);
        float d1 = nv - ret, d2 = (v + dc) - ret;
        vl += fmaxf(d1 * d1, d2 * d2);

        es += ent[idx];
    }

    float rvl = block_reduce(vl,  sm0);
    float res = block_reduce(es,  sm1);
    float rac = block_reduce(act, sm2);
    if (threadIdx.x == 0) {
        atomicAdd(&g_acc[2], (double)rvl);
        atomicAdd(&g_acc[3], (double)res);
        atomicAdd(&g_acc[4], (double)rac);
        __threadfence();
        unsigned tk = atomicAdd(&g_tick2, 1u);
        if (tk == gridDim.x * gridDim.y - 1) {
            volatile double* acc = g_acc;
            double M = (double)MTOT;
            double value_term = 0.25 * (acc[2] / M);   // 0.5*mean * VALUE_LOSS_COEF
            double action_loss = -(acc[4] / M);
            double ent_mean = acc[3] / M;
            out[0] = (float)(value_term + action_loss - 0.01 * ent_mean);
        }
    }
}

// ---------------- launch ------------------------------------------------------
extern "C" void kernel_launch(void* const* d_in, const int* in_sizes, int n_in,
                              void* d_out, int out_size)
{
    const float* rew   = (const float*)d_in[0];
    const float* masks = (const float*)d_in[1];
    const float* bad   = (const float*)d_in[2];
    const float* vp    = (const float*)d_in[3];
    const float* lastv = (const float*)d_in[4];
    const float* lp    = (const float*)d_in[5];
    const float* plp   = (const float*)d_in[6];
    const float* nval  = (const float*)d_in[7];
    const float* ent   = (const float*)d_in[8];
    float* out = (float*)d_out;

    k_init<<<1, 32>>>();

    dim3 grid(NENV / 256, CHUNKS);
    k_coeff<<<grid, 256>>>(rew, masks, bad, vp, lastv);
    k_scan<<<NENV / 256, 256>>>();
    k_main<<<grid, 256>>>(vp, nval, ent, lp, plp, out);
}